// round 1
// baseline (speedup 1.0000x reference)
#include <cuda_runtime.h>
#include <cuda_bf16.h>
#include <math.h>

#define B_SZ 8
#define C_SZ 384
#define N_TOK 1024
#define M_TOT (B_SZ * N_TOK)      // 8192
#define HEADS 8
#define HDIM 48
#define QKV_W (3 * C_SZ)          // 1152

// ---------------- scratch (static device globals; no allocs allowed) ----------
__device__ float g_lnT[C_SZ * M_TOT];       // [384][8192] K-major normed tokens
__device__ float g_qkv[M_TOT * QKV_W];      // [8192][1152]
__device__ float g_aT[C_SZ * M_TOT];        // [384][8192] attention out, K-major
__device__ float g_wqkvT[C_SZ * QKV_W];     // [384][1152]
__device__ float g_wprojT[C_SZ * C_SZ];     // [384][384]

__device__ __forceinline__ float fast_exp2(float x) {
    float y;
    asm("ex2.approx.ftz.f32 %0, %1;" : "=f"(y) : "f"(x));
    return y;
}

// ---------------- weight transpose: W[NOUT][K] -> WT[K][NOUT] ------------------
__global__ void transpose_kernel(const float* __restrict__ W, float* __restrict__ WT,
                                 int NOUT, int K) {
    __shared__ float t[32][33];
    int k0 = blockIdx.x * 32, n0 = blockIdx.y * 32;
    int tx = threadIdx.x & 31, ty = threadIdx.x >> 5;   // 256 threads: 8 rows/pass
    #pragma unroll
    for (int i = ty; i < 32; i += 8)
        t[i][tx] = W[(size_t)(n0 + i) * K + k0 + tx];
    __syncthreads();
    #pragma unroll
    for (int i = ty; i < 32; i += 8)
        WT[(size_t)(k0 + i) * NOUT + n0 + tx] = t[tx][i];
}

// ---------------- LayerNorm: x[B][C][N] tokens -> lnT[c][b*N+n] ---------------
__global__ void ln_kernel(const float* __restrict__ x,
                          const float* __restrict__ lnw,
                          const float* __restrict__ lnb,
                          float* __restrict__ lnT) {
    int b = blockIdx.y;
    int n = blockIdx.x * 128 + threadIdx.x;
    const float* xb = x + (size_t)b * C_SZ * N_TOK + n;
    float s = 0.f, s2 = 0.f;
    #pragma unroll 8
    for (int c = 0; c < C_SZ; c++) {
        float v = xb[(size_t)c * N_TOK];
        s += v; s2 += v * v;
    }
    const float rC = 1.0f / C_SZ;
    float mu = s * rC;
    float var = s2 * rC - mu * mu;
    float r = rsqrtf(var + 1e-6f);
    int m = b * N_TOK + n;
    #pragma unroll 8
    for (int c = 0; c < C_SZ; c++) {
        float v = xb[(size_t)c * N_TOK];
        lnT[(size_t)c * M_TOT + m] = (v - mu) * r * lnw[c] + lnb[c];
    }
}

// ---------------- tiled fp32 GEMM: C[m][n] = sum_k A[k][m] * Bw[k][n] ---------
// A K-major [K][M], Bw K-major [K][N]. 128x128 tile, BK=8, 256 threads, 8x8 micro.
// EPI 0: plain store to C [M][ldc]
// EPI 1: residual add + scatter to out[B][C][N] layout (proj epilogue)
template <int EPI>
__global__ __launch_bounds__(256) void gemm_kernel(
    const float* __restrict__ A, const float* __restrict__ Bw,
    float* __restrict__ C, const float* __restrict__ resid,
    int M, int N, int K) {
    __shared__ float As[8][128];
    __shared__ float Bs[8][128];
    int m0 = blockIdx.x * 128, n0 = blockIdx.y * 128;
    int tid = threadIdx.x;
    int lrow = tid >> 5;            // 0..7
    int lcol = (tid & 31) * 4;      // 0..124
    int row = (tid >> 4) * 8;       // 0..120
    int col = (tid & 15) * 8;       // 0..120
    float acc[8][8];
    #pragma unroll
    for (int i = 0; i < 8; i++)
        #pragma unroll
        for (int j = 0; j < 8; j++) acc[i][j] = 0.f;

    for (int k0 = 0; k0 < K; k0 += 8) {
        *(float4*)&As[lrow][lcol] = *(const float4*)&A[(size_t)(k0 + lrow) * M + m0 + lcol];
        *(float4*)&Bs[lrow][lcol] = *(const float4*)&Bw[(size_t)(k0 + lrow) * N + n0 + lcol];
        __syncthreads();
        #pragma unroll
        for (int kk = 0; kk < 8; kk++) {
            float a[8], b[8];
            *(float4*)&a[0] = *(const float4*)&As[kk][row];
            *(float4*)&a[4] = *(const float4*)&As[kk][row + 4];
            *(float4*)&b[0] = *(const float4*)&Bs[kk][col];
            *(float4*)&b[4] = *(const float4*)&Bs[kk][col + 4];
            #pragma unroll
            for (int i = 0; i < 8; i++)
                #pragma unroll
                for (int j = 0; j < 8; j++) acc[i][j] += a[i] * b[j];
        }
        __syncthreads();
    }

    if (EPI == 0) {
        #pragma unroll
        for (int i = 0; i < 8; i++) {
            size_t base = (size_t)(m0 + row + i) * N + n0 + col;
            #pragma unroll
            for (int j = 0; j < 8; j += 4) {
                float4 v = make_float4(acc[i][j], acc[i][j+1], acc[i][j+2], acc[i][j+3]);
                *(float4*)&C[base + j] = v;
            }
        }
    } else {
        // out[(b*384 + cout)*1024 + ntok] = x[idx] + acc ; m = b*1024 + ntok
        #pragma unroll
        for (int j = 0; j < 8; j++) {
            int cout = n0 + col + j;
            #pragma unroll
            for (int i = 0; i < 8; i += 4) {
                int m = m0 + row + i;
                int bb = m >> 10;
                int nt = m & 1023;
                size_t idx = ((size_t)(bb * C_SZ + cout)) * N_TOK + nt;
                float4 xv = *(const float4*)&resid[idx];
                float4 r = make_float4(acc[i][j] + xv.x, acc[i+1][j] + xv.y,
                                       acc[i+2][j] + xv.z, acc[i+3][j] + xv.w);
                *(float4*)&C[idx] = r;
            }
        }
    }
}

// ---------------- flash attention: one block per (bh, 128 queries) ------------
// q/k/v read from g_qkv[m][1152]; output written K-major to g_aT[c][m].
__global__ __launch_bounds__(128) void attn_kernel(
    const float* __restrict__ qkv, float* __restrict__ aT) {
    int bh = blockIdx.y;
    int b = bh >> 3, h = bh & 7;
    int n = blockIdx.x * 128 + threadIdx.x;   // query token within batch b
    const float SCL = 0.14433756729740643f * 1.44269504088896340f; // 48^-0.5 * log2(e)

    float q[HDIM];
    {
        const float* qr = qkv + ((size_t)(b * N_TOK + n)) * QKV_W + h * HDIM;
        #pragma unroll
        for (int d = 0; d < HDIM; d += 4) {
            float4 t = *(const float4*)&qr[d];
            q[d] = t.x * SCL; q[d+1] = t.y * SCL; q[d+2] = t.z * SCL; q[d+3] = t.w * SCL;
        }
    }
    float o[HDIM];
    #pragma unroll
    for (int d = 0; d < HDIM; d++) o[d] = 0.f;
    float mrun = -1e30f, lsum = 0.f;

    __shared__ float ks[64][HDIM];
    __shared__ float vs[64][HDIM];

    for (int j0 = 0; j0 < N_TOK; j0 += 64) {
        __syncthreads();
        const float* kb = qkv + ((size_t)(b * N_TOK + j0)) * QKV_W + C_SZ + h * HDIM;
        const float* vb = kb + C_SZ;
        // 64 rows * 12 float4 = 768 float4 per tensor; 128 threads -> 6 each
        #pragma unroll
        for (int t = threadIdx.x; t < 768; t += 128) {
            int jj = t / 12, dd = (t % 12) * 4;
            *(float4*)&ks[jj][dd] = *(const float4*)&kb[(size_t)jj * QKV_W + dd];
            *(float4*)&vs[jj][dd] = *(const float4*)&vb[(size_t)jj * QKV_W + dd];
        }
        __syncthreads();

        for (int jj = 0; jj < 64; jj++) {
            const float4* kr = (const float4*)ks[jj];
            float s = 0.f;
            #pragma unroll
            for (int dd = 0; dd < 12; dd++) {
                float4 kv = kr[dd];
                s += q[dd*4+0] * kv.x + q[dd*4+1] * kv.y
                   + q[dd*4+2] * kv.z + q[dd*4+3] * kv.w;
            }
            if (s > mrun) {               // rare after warmup: lazy rescale
                float corr = fast_exp2(mrun - s);
                mrun = s;
                lsum *= corr;
                #pragma unroll
                for (int d = 0; d < HDIM; d++) o[d] *= corr;
            }
            float p = fast_exp2(s - mrun);
            lsum += p;
            const float4* vr = (const float4*)vs[jj];
            #pragma unroll
            for (int dd = 0; dd < 12; dd++) {
                float4 vv = vr[dd];
                o[dd*4+0] += p * vv.x; o[dd*4+1] += p * vv.y;
                o[dd*4+2] += p * vv.z; o[dd*4+3] += p * vv.w;
            }
        }
    }
    float inv = 1.f / lsum;
    int m = b * N_TOK + n;
    #pragma unroll
    for (int d = 0; d < HDIM; d++)
        aT[(size_t)(h * HDIM + d) * M_TOT + m] = o[d] * inv;
}

// ---------------- launch -----------------------------------------------------
extern "C" void kernel_launch(void* const* d_in, const int* in_sizes, int n_in,
                              void* d_out, int out_size) {
    const float* x      = (const float*)d_in[0];
    const float* w_qkv  = (const float*)d_in[1];
    const float* w_proj = (const float*)d_in[2];
    const float* ln_w   = (const float*)d_in[3];
    const float* ln_b   = (const float*)d_in[4];
    float* out = (float*)d_out;

    float *lnT, *qkv, *aT, *wqkvT, *wprojT;
    cudaGetSymbolAddress((void**)&lnT,    g_lnT);
    cudaGetSymbolAddress((void**)&qkv,    g_qkv);
    cudaGetSymbolAddress((void**)&aT,     g_aT);
    cudaGetSymbolAddress((void**)&wqkvT,  g_wqkvT);
    cudaGetSymbolAddress((void**)&wprojT, g_wprojT);

    // 1) weight transposes: [NOUT][K] -> [K][NOUT]
    transpose_kernel<<<dim3(C_SZ/32, QKV_W/32), 256>>>(w_qkv, wqkvT, QKV_W, C_SZ);
    transpose_kernel<<<dim3(C_SZ/32, C_SZ/32), 256>>>(w_proj, wprojT, C_SZ, C_SZ);

    // 2) layernorm -> lnT [384][8192]
    ln_kernel<<<dim3(N_TOK/128, B_SZ), 128>>>(x, ln_w, ln_b, lnT);

    // 3) QKV GEMM: [8192 x 1152] = lnT^T @ wqkvT
    gemm_kernel<0><<<dim3(M_TOT/128, QKV_W/128), 256>>>(lnT, wqkvT, qkv, nullptr,
                                                        M_TOT, QKV_W, C_SZ);

    // 4) attention -> aT [384][8192]
    attn_kernel<<<dim3(N_TOK/128, B_SZ*HEADS), 128>>>(qkv, aT);

    // 5) proj GEMM + residual, scattered into [B][C][H][W]
    gemm_kernel<1><<<dim3(M_TOT/128, C_SZ/128), 256>>>(aT, wprojT, out, x,
                                                       M_TOT, C_SZ, C_SZ);
}

// round 3
// speedup vs baseline: 1.2430x; 1.2430x over previous
#include <cuda_runtime.h>
#include <cstdint>
#include <math.h>

#define B_SZ 8
#define C_SZ 384
#define N_TOK 1024
#define M_TOT (B_SZ * N_TOK)      // 8192
#define HEADS 8
#define HDIM 48
#define QKV_W (3 * C_SZ)          // 1152

// ---------------- scratch ------------------------------------------------------
__device__ float g_ln[M_TOT * C_SZ];     // [8192][384] tf32-rounded LN output
__device__ float g_qkv[M_TOT * QKV_W];   // [8192][1152]
__device__ float g_att[M_TOT * C_SZ];    // [8192][384] tf32-rounded attention out
__device__ float g_wq[QKV_W * C_SZ];     // tf32-rounded w_qkv [1152][384]
__device__ float g_wp[C_SZ * C_SZ];      // tf32-rounded w_proj [384][384]

// ---------------- helpers ------------------------------------------------------
__device__ __forceinline__ float fast_exp2(float x) {
    float y; asm("ex2.approx.ftz.f32 %0, %1;" : "=f"(y) : "f"(x)); return y;
}
__device__ __forceinline__ float tf32r(float x) {
    uint32_t u; asm("cvt.rna.tf32.f32 %0, %1;" : "=r"(u) : "f"(x));
    return __uint_as_float(u);
}
__device__ __forceinline__ uint32_t smem_u32(const void* p) {
    uint32_t a;
    asm("{ .reg .u64 t; cvta.to.shared.u64 t, %1; cvt.u32.u64 %0, t; }" : "=r"(a) : "l"(p));
    return a;
}
__device__ __forceinline__ void cp16(uint32_t dst, const void* src) {
    asm volatile("cp.async.cg.shared.global [%0], [%1], 16;" :: "r"(dst), "l"(src) : "memory");
}
#define CP_COMMIT() asm volatile("cp.async.commit_group;" ::: "memory")
#define CP_WAIT2()  asm volatile("cp.async.wait_group 2;" ::: "memory")

__device__ __forceinline__ void mma_tf32(float* c, const uint32_t* a, const uint32_t* b) {
    asm volatile(
        "mma.sync.aligned.m16n8k8.row.col.f32.tf32.tf32.f32 "
        "{%0,%1,%2,%3}, {%4,%5,%6,%7}, {%8,%9}, {%0,%1,%2,%3};"
        : "+f"(c[0]), "+f"(c[1]), "+f"(c[2]), "+f"(c[3])
        : "r"(a[0]), "r"(a[1]), "r"(a[2]), "r"(a[3]), "r"(b[0]), "r"(b[1]));
}

// ---------------- tf32 rounding of weights -------------------------------------
__global__ void round_kernel(const float* __restrict__ in, float* __restrict__ out, int n) {
    int i = blockIdx.x * 256 + threadIdx.x;
    if (i < n) out[i] = tf32r(in[i]);
}

// ---------------- LayerNorm: x[B][C][N] -> ln[m][c] row-major, tf32 ------------
__global__ void ln_kernel(const float* __restrict__ x,
                          const float* __restrict__ lnw,
                          const float* __restrict__ lnb,
                          float* __restrict__ ln) {
    int b = blockIdx.y;
    int n = blockIdx.x * 128 + threadIdx.x;
    const float* xb = x + (size_t)b * C_SZ * N_TOK + n;
    float s = 0.f, s2 = 0.f;
    #pragma unroll 8
    for (int c = 0; c < C_SZ; c++) {
        float v = xb[(size_t)c * N_TOK];
        s += v; s2 += v * v;
    }
    const float rC = 1.0f / C_SZ;
    float mu = s * rC;
    float var = s2 * rC - mu * mu;
    float r = rsqrtf(var + 1e-6f);
    float* lr = ln + (size_t)(b * N_TOK + n) * C_SZ;
    #pragma unroll 4
    for (int c = 0; c < C_SZ; c += 4) {
        float4 w;
        w.x = tf32r((xb[(size_t)(c+0) * N_TOK] - mu) * r * lnw[c+0] + lnb[c+0]);
        w.y = tf32r((xb[(size_t)(c+1) * N_TOK] - mu) * r * lnw[c+1] + lnb[c+1]);
        w.z = tf32r((xb[(size_t)(c+2) * N_TOK] - mu) * r * lnw[c+2] + lnb[c+2]);
        w.w = tf32r((xb[(size_t)(c+3) * N_TOK] - mu) * r * lnw[c+3] + lnb[c+3]);
        *(float4*)&lr[c] = w;
    }
}

// ---------------- mma.sync tf32 GEMM --------------------------------------------
// C[m][n] = sum_k A[m][k] * Bw[n][k];  A [M][384], Bw [N][384] row-major tf32.
// CTA 128x128, 128 threads (2x2 warps of 64x64), BK=16, 4-stage cp.async ring.
// smem per stage: A[128][20] + B[128][20] floats (stride 20 -> conflict-free frags)
#define BK 16
#define SSTRIDE 20
#define OPFLOATS (128 * SSTRIDE)            // 2560 floats per operand
#define STFLOATS (2 * OPFLOATS)             // 5120 floats per stage
#define GSMEM (4 * STFLOATS * 4)            // 81920 bytes

template <int EPI>
__global__ __launch_bounds__(128) void gemm_mma(
    const float* __restrict__ A, const float* __restrict__ Bw,
    float* __restrict__ Cout, const float* __restrict__ resid, int Nld) {
    extern __shared__ float sm[];
    const uint32_t usm = smem_u32(sm);
    const int tid = threadIdx.x;
    const int wid = tid >> 5, lane = tid & 31;
    const int g = lane >> 2, tig = lane & 3;
    const int m0 = blockIdx.x * 128, n0 = blockIdx.y * 128;
    const int warp_m = (wid & 1) * 64, warp_n = (wid >> 1) * 64;
    const int NSTG = C_SZ / BK;             // 24

    float acc[4][8][4];
    #pragma unroll
    for (int i = 0; i < 4; i++)
        #pragma unroll
        for (int j = 0; j < 8; j++)
            #pragma unroll
            for (int e = 0; e < 4; e++) acc[i][j][e] = 0.f;

    // issue stage s into ring buffer s&3
    auto issue = [&](int s) {
        int k0 = s * BK;
        uint32_t base = usm + (uint32_t)(s & 3) * (STFLOATS * 4);
        #pragma unroll
        for (int i = 0; i < 4; i++) {
            int id = tid + i * 128;          // 0..511
            int row = id >> 2;               // 0..127
            int c = (id & 3) * 4;            // 0,4,8,12
            uint32_t off = (uint32_t)(row * SSTRIDE + c) * 4;
            cp16(base + off, &A[(size_t)(m0 + row) * C_SZ + k0 + c]);
            cp16(base + OPFLOATS * 4 + off, &Bw[(size_t)(n0 + row) * C_SZ + k0 + c]);
        }
    };

    issue(0); CP_COMMIT();
    issue(1); CP_COMMIT();
    issue(2); CP_COMMIT();

    for (int s = 0; s < NSTG; s++) {
        CP_WAIT2();
        __syncthreads();
        if (s + 3 < NSTG) issue(s + 3);
        CP_COMMIT();

        const float* As = sm + (s & 3) * STFLOATS;
        const float* Bs = As + OPFLOATS;
        #pragma unroll
        for (int kk = 0; kk < BK; kk += 8) {
            uint32_t af[4][4], bf[8][2];
            #pragma unroll
            for (int mt = 0; mt < 4; mt++) {
                int r = warp_m + mt * 16 + g;
                af[mt][0] = __float_as_uint(As[(r    ) * SSTRIDE + kk + tig]);
                af[mt][1] = __float_as_uint(As[(r + 8) * SSTRIDE + kk + tig]);
                af[mt][2] = __float_as_uint(As[(r    ) * SSTRIDE + kk + tig + 4]);
                af[mt][3] = __float_as_uint(As[(r + 8) * SSTRIDE + kk + tig + 4]);
            }
            #pragma unroll
            for (int nt = 0; nt < 8; nt++) {
                int r = warp_n + nt * 8 + g;
                bf[nt][0] = __float_as_uint(Bs[r * SSTRIDE + kk + tig]);
                bf[nt][1] = __float_as_uint(Bs[r * SSTRIDE + kk + tig + 4]);
            }
            #pragma unroll
            for (int mt = 0; mt < 4; mt++)
                #pragma unroll
                for (int nt = 0; nt < 8; nt++)
                    mma_tf32(acc[mt][nt], af[mt], bf[nt]);
        }
        __syncthreads();
    }

    // epilogue
    #pragma unroll
    for (int mt = 0; mt < 4; mt++) {
        int row = m0 + warp_m + mt * 16 + g;
        #pragma unroll
        for (int nt = 0; nt < 8; nt++) {
            int col = n0 + warp_n + nt * 8 + tig * 2;
            float* c = acc[mt][nt];
            if (EPI == 0) {
                *(float2*)&Cout[(size_t)row * Nld + col] = make_float2(c[0], c[1]);
                *(float2*)&Cout[(size_t)(row + 8) * Nld + col] = make_float2(c[2], c[3]);
            } else {
                int b0 = row >> 10, t0 = row & 1023;
                int b1 = (row + 8) >> 10, t1 = (row + 8) & 1023;
                size_t i00 = ((size_t)b0 * C_SZ + col) * N_TOK + t0;
                size_t i01 = i00 + N_TOK;
                size_t i10 = ((size_t)b1 * C_SZ + col) * N_TOK + t1;
                size_t i11 = i10 + N_TOK;
                Cout[i00] = resid[i00] + c[0];
                Cout[i01] = resid[i01] + c[1];
                Cout[i10] = resid[i10] + c[2];
                Cout[i11] = resid[i11] + c[3];
            }
        }
    }
}

// ---------------- flash attention (SIMT fp32) ----------------------------------
__global__ __launch_bounds__(128) void attn_kernel(
    const float* __restrict__ qkv, float* __restrict__ att) {
    int bh = blockIdx.y;
    int b = bh >> 3, h = bh & 7;
    int n = blockIdx.x * 128 + threadIdx.x;
    const float SCL = 0.14433756729740643f * 1.44269504088896340f;

    float q[HDIM];
    {
        const float* qr = qkv + ((size_t)(b * N_TOK + n)) * QKV_W + h * HDIM;
        #pragma unroll
        for (int d = 0; d < HDIM; d += 4) {
            float4 t = *(const float4*)&qr[d];
            q[d] = t.x * SCL; q[d+1] = t.y * SCL; q[d+2] = t.z * SCL; q[d+3] = t.w * SCL;
        }
    }
    float o[HDIM];
    #pragma unroll
    for (int d = 0; d < HDIM; d++) o[d] = 0.f;
    float mrun = -1e30f, lsum = 0.f;

    __shared__ float ks[64][HDIM];
    __shared__ float vs[64][HDIM];

    for (int j0 = 0; j0 < N_TOK; j0 += 64) {
        __syncthreads();
        const float* kb = qkv + ((size_t)(b * N_TOK + j0)) * QKV_W + C_SZ + h * HDIM;
        const float* vb = kb + C_SZ;
        #pragma unroll
        for (int t = threadIdx.x; t < 768; t += 128) {
            int jj = t / 12, dd = (t % 12) * 4;
            *(float4*)&ks[jj][dd] = *(const float4*)&kb[(size_t)jj * QKV_W + dd];
            *(float4*)&vs[jj][dd] = *(const float4*)&vb[(size_t)jj * QKV_W + dd];
        }
        __syncthreads();

        for (int jj = 0; jj < 64; jj++) {
            const float4* kr = (const float4*)ks[jj];
            float s = 0.f;
            #pragma unroll
            for (int dd = 0; dd < 12; dd++) {
                float4 kv = kr[dd];
                s += q[dd*4+0] * kv.x + q[dd*4+1] * kv.y
                   + q[dd*4+2] * kv.z + q[dd*4+3] * kv.w;
            }
            if (s > mrun) {
                float corr = fast_exp2(mrun - s);
                mrun = s;
                lsum *= corr;
                #pragma unroll
                for (int d = 0; d < HDIM; d++) o[d] *= corr;
            }
            float p = fast_exp2(s - mrun);
            lsum += p;
            const float4* vr = (const float4*)vs[jj];
            #pragma unroll
            for (int dd = 0; dd < 12; dd++) {
                float4 vv = vr[dd];
                o[dd*4+0] += p * vv.x; o[dd*4+1] += p * vv.y;
                o[dd*4+2] += p * vv.z; o[dd*4+3] += p * vv.w;
            }
        }
    }
    float inv = 1.f / lsum;
    float* orow = att + ((size_t)(b * N_TOK + n)) * C_SZ + h * HDIM;
    #pragma unroll
    for (int d = 0; d < HDIM; d += 4) {
        float4 w;
        w.x = tf32r(o[d+0] * inv); w.y = tf32r(o[d+1] * inv);
        w.z = tf32r(o[d+2] * inv); w.w = tf32r(o[d+3] * inv);
        *(float4*)&orow[d] = w;
    }
}

// ---------------- launch --------------------------------------------------------
extern "C" void kernel_launch(void* const* d_in, const int* in_sizes, int n_in,
                              void* d_out, int out_size) {
    const float* x      = (const float*)d_in[0];
    const float* w_qkv  = (const float*)d_in[1];
    const float* w_proj = (const float*)d_in[2];
    const float* ln_w   = (const float*)d_in[3];
    const float* ln_b   = (const float*)d_in[4];
    float* out = (float*)d_out;

    float *ln, *qkv, *att, *wq, *wp;
    cudaGetSymbolAddress((void**)&ln,  g_ln);
    cudaGetSymbolAddress((void**)&qkv, g_qkv);
    cudaGetSymbolAddress((void**)&att, g_att);
    cudaGetSymbolAddress((void**)&wq,  g_wq);
    cudaGetSymbolAddress((void**)&wp,  g_wp);

    cudaFuncSetAttribute(gemm_mma<0>, cudaFuncAttributeMaxDynamicSharedMemorySize, GSMEM);
    cudaFuncSetAttribute(gemm_mma<1>, cudaFuncAttributeMaxDynamicSharedMemorySize, GSMEM);

    // 1) tf32-round weights (consumed as [N][K] directly — no transpose needed)
    round_kernel<<<(QKV_W * C_SZ + 255) / 256, 256>>>(w_qkv, wq, QKV_W * C_SZ);
    round_kernel<<<(C_SZ * C_SZ + 255) / 256, 256>>>(w_proj, wp, C_SZ * C_SZ);

    // 2) layernorm -> ln [8192][384] tf32
    ln_kernel<<<dim3(N_TOK / 128, B_SZ), 128>>>(x, ln_w, ln_b, ln);

    // 3) QKV GEMM (mma.sync tf32): [8192 x 1152]
    gemm_mma<0><<<dim3(M_TOT / 128, QKV_W / 128), 128, GSMEM>>>(ln, wq, qkv, nullptr, QKV_W);

    // 4) attention -> att [8192][384] tf32
    attn_kernel<<<dim3(N_TOK / 128, B_SZ * HEADS), 128>>>(qkv, att);

    // 5) proj GEMM (mma.sync tf32) + residual, scattered into [B][C][H][W]
    gemm_mma<1><<<dim3(M_TOT / 128, C_SZ / 128), 128, GSMEM>>>(att, wp, out, x, C_SZ);
}

// round 4
// speedup vs baseline: 3.3464x; 2.6923x over previous
#include <cuda_runtime.h>
#include <cstdint>
#include <math.h>

#define B_SZ 8
#define C_SZ 384
#define N_TOK 1024
#define M_TOT (B_SZ * N_TOK)      // 8192
#define HEADS 8
#define HDIM 48
#define QKV_W (3 * C_SZ)          // 1152

// ---------------- scratch ------------------------------------------------------
__device__ float g_ln[M_TOT * C_SZ];     // [8192][384] tf32 LN output
__device__ float g_qkv[M_TOT * QKV_W];   // [8192][1152] tf32
__device__ float g_att[M_TOT * C_SZ];    // [8192][384] tf32 attention out
__device__ float g_wq[QKV_W * C_SZ];     // tf32 w_qkv [1152][384]
__device__ float g_wp[C_SZ * C_SZ];      // tf32 w_proj [384][384]

// ---------------- helpers ------------------------------------------------------
__device__ __forceinline__ float fast_exp2(float x) {
    float y; asm("ex2.approx.ftz.f32 %0, %1;" : "=f"(y) : "f"(x)); return y;
}
__device__ __forceinline__ float tf32r(float x) {
    uint32_t u; asm("cvt.rna.tf32.f32 %0, %1;" : "=r"(u) : "f"(x));
    return __uint_as_float(u);
}
__device__ __forceinline__ uint32_t smem_u32(const void* p) {
    uint32_t a;
    asm("{ .reg .u64 t; cvta.to.shared.u64 t, %1; cvt.u32.u64 %0, t; }" : "=r"(a) : "l"(p));
    return a;
}
__device__ __forceinline__ void cp16(uint32_t dst, const void* src) {
    asm volatile("cp.async.cg.shared.global [%0], [%1], 16;" :: "r"(dst), "l"(src) : "memory");
}
#define CP_COMMIT() asm volatile("cp.async.commit_group;" ::: "memory")

__device__ __forceinline__ void mma_tf32(float* c, const uint32_t* a, const uint32_t* b) {
    asm volatile(
        "mma.sync.aligned.m16n8k8.row.col.f32.tf32.tf32.f32 "
        "{%0,%1,%2,%3}, {%4,%5,%6,%7}, {%8,%9}, {%0,%1,%2,%3};"
        : "+f"(c[0]), "+f"(c[1]), "+f"(c[2]), "+f"(c[3])
        : "r"(a[0]), "r"(a[1]), "r"(a[2]), "r"(a[3]), "r"(b[0]), "r"(b[1]));
}

// ---------------- tf32 rounding of weights -------------------------------------
__global__ void round_kernel(const float* __restrict__ in, float* __restrict__ out, int n) {
    int i = blockIdx.x * 256 + threadIdx.x;
    if (i < n) out[i] = tf32r(in[i]);
}

// ---------------- LayerNorm: x[B][C][N] -> ln[m][c] row-major, tf32 ------------
__global__ void ln_kernel(const float* __restrict__ x,
                          const float* __restrict__ lnw,
                          const float* __restrict__ lnb,
                          float* __restrict__ ln) {
    int b = blockIdx.y;
    int n = blockIdx.x * 128 + threadIdx.x;
    const float* xb = x + (size_t)b * C_SZ * N_TOK + n;
    float s = 0.f, s2 = 0.f;
    #pragma unroll 8
    for (int c = 0; c < C_SZ; c++) {
        float v = xb[(size_t)c * N_TOK];
        s += v; s2 += v * v;
    }
    const float rC = 1.0f / C_SZ;
    float mu = s * rC;
    float var = s2 * rC - mu * mu;
    float r = rsqrtf(var + 1e-6f);
    float* lr = ln + (size_t)(b * N_TOK + n) * C_SZ;
    #pragma unroll 4
    for (int c = 0; c < C_SZ; c += 4) {
        float4 w;
        w.x = tf32r((xb[(size_t)(c+0) * N_TOK] - mu) * r * lnw[c+0] + lnb[c+0]);
        w.y = tf32r((xb[(size_t)(c+1) * N_TOK] - mu) * r * lnw[c+1] + lnb[c+1]);
        w.z = tf32r((xb[(size_t)(c+2) * N_TOK] - mu) * r * lnw[c+2] + lnb[c+2]);
        w.w = tf32r((xb[(size_t)(c+3) * N_TOK] - mu) * r * lnw[c+3] + lnb[c+3]);
        *(float4*)&lr[c] = w;
    }
}

// ---------------- mma.sync tf32 GEMM --------------------------------------------
#define BK 16
#define SSTRIDE 20
#define OPFLOATS (128 * SSTRIDE)
#define STFLOATS (2 * OPFLOATS)
#define GSMEM (4 * STFLOATS * 4)

template <int EPI>
__global__ __launch_bounds__(128) void gemm_mma(
    const float* __restrict__ A, const float* __restrict__ Bw,
    float* __restrict__ Cout, const float* __restrict__ resid, int Nld) {
    extern __shared__ float sm[];
    const uint32_t usm = smem_u32(sm);
    const int tid = threadIdx.x;
    const int wid = tid >> 5, lane = tid & 31;
    const int g = lane >> 2, tig = lane & 3;
    const int m0 = blockIdx.x * 128, n0 = blockIdx.y * 128;
    const int warp_m = (wid & 1) * 64, warp_n = (wid >> 1) * 64;
    const int NSTG = C_SZ / BK;

    float acc[4][8][4];
    #pragma unroll
    for (int i = 0; i < 4; i++)
        #pragma unroll
        for (int j = 0; j < 8; j++)
            #pragma unroll
            for (int e = 0; e < 4; e++) acc[i][j][e] = 0.f;

    auto issue = [&](int s) {
        int k0 = s * BK;
        uint32_t base = usm + (uint32_t)(s & 3) * (STFLOATS * 4);
        #pragma unroll
        for (int i = 0; i < 4; i++) {
            int id = tid + i * 128;
            int row = id >> 2;
            int c = (id & 3) * 4;
            uint32_t off = (uint32_t)(row * SSTRIDE + c) * 4;
            cp16(base + off, &A[(size_t)(m0 + row) * C_SZ + k0 + c]);
            cp16(base + OPFLOATS * 4 + off, &Bw[(size_t)(n0 + row) * C_SZ + k0 + c]);
        }
    };

    issue(0); CP_COMMIT();
    issue(1); CP_COMMIT();
    issue(2); CP_COMMIT();

    for (int s = 0; s < NSTG; s++) {
        asm volatile("cp.async.wait_group 2;" ::: "memory");
        __syncthreads();
        if (s + 3 < NSTG) issue(s + 3);
        CP_COMMIT();

        const float* As = sm + (s & 3) * STFLOATS;
        const float* Bs = As + OPFLOATS;
        #pragma unroll
        for (int kk = 0; kk < BK; kk += 8) {
            uint32_t af[4][4], bf[8][2];
            #pragma unroll
            for (int mt = 0; mt < 4; mt++) {
                int r = warp_m + mt * 16 + g;
                af[mt][0] = __float_as_uint(As[(r    ) * SSTRIDE + kk + tig]);
                af[mt][1] = __float_as_uint(As[(r + 8) * SSTRIDE + kk + tig]);
                af[mt][2] = __float_as_uint(As[(r    ) * SSTRIDE + kk + tig + 4]);
                af[mt][3] = __float_as_uint(As[(r + 8) * SSTRIDE + kk + tig + 4]);
            }
            #pragma unroll
            for (int nt = 0; nt < 8; nt++) {
                int r = warp_n + nt * 8 + g;
                bf[nt][0] = __float_as_uint(Bs[r * SSTRIDE + kk + tig]);
                bf[nt][1] = __float_as_uint(Bs[r * SSTRIDE + kk + tig + 4]);
            }
            #pragma unroll
            for (int mt = 0; mt < 4; mt++)
                #pragma unroll
                for (int nt = 0; nt < 8; nt++)
                    mma_tf32(acc[mt][nt], af[mt], bf[nt]);
        }
        __syncthreads();
    }

    #pragma unroll
    for (int mt = 0; mt < 4; mt++) {
        int row = m0 + warp_m + mt * 16 + g;
        #pragma unroll
        for (int nt = 0; nt < 8; nt++) {
            int col = n0 + warp_n + nt * 8 + tig * 2;
            float* c = acc[mt][nt];
            if (EPI == 0) {
                // round to tf32: consumed by tensor-core attention
                *(float2*)&Cout[(size_t)row * Nld + col] =
                    make_float2(tf32r(c[0]), tf32r(c[1]));
                *(float2*)&Cout[(size_t)(row + 8) * Nld + col] =
                    make_float2(tf32r(c[2]), tf32r(c[3]));
            } else {
                int b0 = row >> 10, t0 = row & 1023;
                int b1 = (row + 8) >> 10, t1 = (row + 8) & 1023;
                size_t i00 = ((size_t)b0 * C_SZ + col) * N_TOK + t0;
                size_t i01 = i00 + N_TOK;
                size_t i10 = ((size_t)b1 * C_SZ + col) * N_TOK + t1;
                size_t i11 = i10 + N_TOK;
                Cout[i00] = resid[i00] + c[0];
                Cout[i01] = resid[i01] + c[1];
                Cout[i10] = resid[i10] + c[2];
                Cout[i11] = resid[i11] + c[3];
            }
        }
    }
}

// ---------------- tensor-core flash attention -----------------------------------
// CTA: 128 queries of one (b,h); 8 warps x 16 rows. K/V tiles of 64 keys,
// double-buffered cp.async. S and P live in mma fragments; online softmax.
#define BC 64
#define KSTRIDE 52
#define VSTRIDE 56
#define KST (BC * KSTRIDE)
#define VST (BC * VSTRIDE)
#define ABUF (KST + VST)
#define ASMEM (2 * ABUF * 4)     // 55296 bytes

__global__ __launch_bounds__(256) void attn_mma(
    const float* __restrict__ qkv, float* __restrict__ att) {
    extern __shared__ float sm[];
    const uint32_t usm = smem_u32(sm);
    const int tid = threadIdx.x;
    const int wid = tid >> 5, lane = tid & 31;
    const int g = lane >> 2, tig = lane & 3;
    const int bh = blockIdx.y;
    const int b = bh >> 3, h = bh & 7;
    const int q0 = blockIdx.x * 128 + wid * 16;
    const float QS = 0.14433756729740643f * 1.44269504088896340f; // d^-1/2 * log2(e)

    // Q fragments (rows q0+g, q0+g+8), scale folded, rna-rounded
    uint32_t qa[6][4];
    {
        const float* Qb = qkv + ((size_t)(b * N_TOK + q0)) * QKV_W + h * HDIM;
        #pragma unroll
        for (int kk = 0; kk < 6; kk++) {
            qa[kk][0] = __float_as_uint(tf32r(Qb[(size_t)g * QKV_W + kk*8 + tig] * QS));
            qa[kk][1] = __float_as_uint(tf32r(Qb[(size_t)(g+8) * QKV_W + kk*8 + tig] * QS));
            qa[kk][2] = __float_as_uint(tf32r(Qb[(size_t)g * QKV_W + kk*8 + tig + 4] * QS));
            qa[kk][3] = __float_as_uint(tf32r(Qb[(size_t)(g+8) * QKV_W + kk*8 + tig + 4] * QS));
        }
    }

    float o[6][4];
    #pragma unroll
    for (int nt = 0; nt < 6; nt++)
        #pragma unroll
        for (int e = 0; e < 4; e++) o[nt][e] = 0.f;
    float mr0 = -1e30f, mr1 = -1e30f, l0 = 0.f, l1 = 0.f;

    auto issue = [&](int t) {
        int j0 = t * BC;
        uint32_t base = usm + (uint32_t)(t & 1) * (ABUF * 4);
        const float* kb = qkv + ((size_t)(b * N_TOK + j0)) * QKV_W + C_SZ + h * HDIM;
        const float* vb = kb + C_SZ;
        #pragma unroll
        for (int i = 0; i < 3; i++) {
            int id = tid + i * 256;            // 0..767
            int r = id / 12, c = (id % 12) * 4;
            cp16(base + (uint32_t)(r * KSTRIDE + c) * 4, kb + (size_t)r * QKV_W + c);
            cp16(base + (uint32_t)(KST + r * VSTRIDE + c) * 4, vb + (size_t)r * QKV_W + c);
        }
    };

    issue(0); CP_COMMIT();

    for (int t = 0; t < N_TOK / BC; t++) {
        if (t + 1 < N_TOK / BC) { issue(t + 1); CP_COMMIT(); }
        if (t + 1 < N_TOK / BC) {
            asm volatile("cp.async.wait_group 1;" ::: "memory");
        } else {
            asm volatile("cp.async.wait_group 0;" ::: "memory");
        }
        __syncthreads();

        const float* ks = sm + (t & 1) * ABUF;
        const float* vs = ks + KST;

        // ---- S = Q K^T (16 x 64), fragments sc[nt][4] ----
        float sc[8][4];
        #pragma unroll
        for (int nt = 0; nt < 8; nt++)
            #pragma unroll
            for (int e = 0; e < 4; e++) sc[nt][e] = 0.f;
        #pragma unroll
        for (int kk = 0; kk < 6; kk++) {
            #pragma unroll
            for (int nt = 0; nt < 8; nt++) {
                uint32_t bf[2];
                bf[0] = __float_as_uint(ks[(nt*8 + g) * KSTRIDE + kk*8 + tig]);
                bf[1] = __float_as_uint(ks[(nt*8 + g) * KSTRIDE + kk*8 + tig + 4]);
                mma_tf32(sc[nt], qa[kk], bf);
            }
        }

        // ---- online softmax (log2 domain) ----
        float mt0 = -1e30f, mt1 = -1e30f;
        #pragma unroll
        for (int nt = 0; nt < 8; nt++) {
            mt0 = fmaxf(mt0, fmaxf(sc[nt][0], sc[nt][1]));
            mt1 = fmaxf(mt1, fmaxf(sc[nt][2], sc[nt][3]));
        }
        mt0 = fmaxf(mt0, __shfl_xor_sync(0xffffffffu, mt0, 1));
        mt0 = fmaxf(mt0, __shfl_xor_sync(0xffffffffu, mt0, 2));
        mt1 = fmaxf(mt1, __shfl_xor_sync(0xffffffffu, mt1, 1));
        mt1 = fmaxf(mt1, __shfl_xor_sync(0xffffffffu, mt1, 2));
        float mn0 = fmaxf(mr0, mt0), mn1 = fmaxf(mr1, mt1);
        float al0 = fast_exp2(mr0 - mn0), al1 = fast_exp2(mr1 - mn1);
        mr0 = mn0; mr1 = mn1;

        float s0 = 0.f, s1 = 0.f;
        #pragma unroll
        for (int nt = 0; nt < 8; nt++) {
            sc[nt][0] = fast_exp2(sc[nt][0] - mn0);
            sc[nt][1] = fast_exp2(sc[nt][1] - mn0);
            sc[nt][2] = fast_exp2(sc[nt][2] - mn1);
            sc[nt][3] = fast_exp2(sc[nt][3] - mn1);
            s0 += sc[nt][0] + sc[nt][1];
            s1 += sc[nt][2] + sc[nt][3];
        }
        s0 += __shfl_xor_sync(0xffffffffu, s0, 1);
        s0 += __shfl_xor_sync(0xffffffffu, s0, 2);
        s1 += __shfl_xor_sync(0xffffffffu, s1, 1);
        s1 += __shfl_xor_sync(0xffffffffu, s1, 2);
        l0 = l0 * al0 + s0;
        l1 = l1 * al1 + s1;
        #pragma unroll
        for (int nt = 0; nt < 6; nt++) {
            o[nt][0] *= al0; o[nt][1] *= al0;
            o[nt][2] *= al1; o[nt][3] *= al1;
        }

        // ---- O += P V : relayout P (C-frag -> A-frag) via quad shuffles ----
        const int base01 = (lane & ~3) + (tig >> 1);
        const int base23 = base01 + 2;
        #pragma unroll
        for (int kt = 0; kt < 8; kt++) {
            float c0a = __shfl_sync(0xffffffffu, sc[kt][0], base01);
            float c1a = __shfl_sync(0xffffffffu, sc[kt][1], base01);
            float c2a = __shfl_sync(0xffffffffu, sc[kt][2], base01);
            float c3a = __shfl_sync(0xffffffffu, sc[kt][3], base01);
            float c0b = __shfl_sync(0xffffffffu, sc[kt][0], base23);
            float c1b = __shfl_sync(0xffffffffu, sc[kt][1], base23);
            float c2b = __shfl_sync(0xffffffffu, sc[kt][2], base23);
            float c3b = __shfl_sync(0xffffffffu, sc[kt][3], base23);
            bool odd = (tig & 1);
            uint32_t pa[4];
            pa[0] = __float_as_uint(tf32r(odd ? c1a : c0a));
            pa[1] = __float_as_uint(tf32r(odd ? c3a : c2a));
            pa[2] = __float_as_uint(tf32r(odd ? c1b : c0b));
            pa[3] = __float_as_uint(tf32r(odd ? c3b : c2b));
            #pragma unroll
            for (int nt = 0; nt < 6; nt++) {
                uint32_t bf[2];
                bf[0] = __float_as_uint(vs[(kt*8 + tig) * VSTRIDE + nt*8 + g]);
                bf[1] = __float_as_uint(vs[(kt*8 + tig + 4) * VSTRIDE + nt*8 + g]);
                mma_tf32(o[nt], pa, bf);
            }
        }
        __syncthreads();
    }

    // ---- epilogue: O / l, tf32-rounded, row-major [m][384] ----
    float inv0 = 1.f / l0, inv1 = 1.f / l1;
    float* or0 = att + ((size_t)(b * N_TOK + q0 + g)) * C_SZ + h * HDIM;
    float* or1 = or0 + (size_t)8 * C_SZ;
    #pragma unroll
    for (int nt = 0; nt < 6; nt++) {
        *(float2*)&or0[nt*8 + tig*2] =
            make_float2(tf32r(o[nt][0] * inv0), tf32r(o[nt][1] * inv0));
        *(float2*)&or1[nt*8 + tig*2] =
            make_float2(tf32r(o[nt][2] * inv1), tf32r(o[nt][3] * inv1));
    }
}

// ---------------- launch --------------------------------------------------------
extern "C" void kernel_launch(void* const* d_in, const int* in_sizes, int n_in,
                              void* d_out, int out_size) {
    const float* x      = (const float*)d_in[0];
    const float* w_qkv  = (const float*)d_in[1];
    const float* w_proj = (const float*)d_in[2];
    const float* ln_w   = (const float*)d_in[3];
    const float* ln_b   = (const float*)d_in[4];
    float* out = (float*)d_out;

    float *ln, *qkv, *att, *wq, *wp;
    cudaGetSymbolAddress((void**)&ln,  g_ln);
    cudaGetSymbolAddress((void**)&qkv, g_qkv);
    cudaGetSymbolAddress((void**)&att, g_att);
    cudaGetSymbolAddress((void**)&wq,  g_wq);
    cudaGetSymbolAddress((void**)&wp,  g_wp);

    cudaFuncSetAttribute(gemm_mma<0>, cudaFuncAttributeMaxDynamicSharedMemorySize, GSMEM);
    cudaFuncSetAttribute(gemm_mma<1>, cudaFuncAttributeMaxDynamicSharedMemorySize, GSMEM);
    cudaFuncSetAttribute(attn_mma, cudaFuncAttributeMaxDynamicSharedMemorySize, ASMEM);

    round_kernel<<<(QKV_W * C_SZ + 255) / 256, 256>>>(w_qkv, wq, QKV_W * C_SZ);
    round_kernel<<<(C_SZ * C_SZ + 255) / 256, 256>>>(w_proj, wp, C_SZ * C_SZ);

    ln_kernel<<<dim3(N_TOK / 128, B_SZ), 128>>>(x, ln_w, ln_b, ln);

    gemm_mma<0><<<dim3(M_TOT / 128, QKV_W / 128), 128, GSMEM>>>(ln, wq, qkv, nullptr, QKV_W);

    attn_mma<<<dim3(N_TOK / 128, B_SZ * HEADS), 256, ASMEM>>>(qkv, att);

    gemm_mma<1><<<dim3(M_TOT / 128, C_SZ / 128), 128, GSMEM>>>(att, wp, out, x, C_SZ);
}